// round 16
// baseline (speedup 1.0000x reference)
#include <cuda_runtime.h>

// inputs: float32 [16, 64, 256, 256] NCHW
#define NB      16
#define NC      64
#define HW4     16384                 // float4 per (n,c) slice
#define SLICE4  (NC * HW4)
#define TPB     512
#define NWARP   (TPB / 32)            // 16
#define EPS     1e-5f

#define NR      8                     // rounds (channel groups of 8)
#define CPR     8                     // channels per round
#define BPC     64                    // blocks per channel
#define NBLK    512                   // all co-resident (148 SMs * 4 slots)
#define ITERS   8                     // float4 per thread per tile (64 KB tile)
#define STASH   3                     // float4 per thread stashed in smem
                                      // smem: 2*3*512*16B = 48 KB/block; x4 = 192 KB/SM <= 228

// Zero-initialized device state; kernel restores zeros before exiting.
__device__ float g_sum[NC];
__device__ float g_sq [NC];
__device__ float g_scale[NC];
__device__ float g_bias [NC];
__device__ int   g_done [NC];
__device__ int   g_ready[NC];
__device__ int   g_fin;

// Reduce one 64 KB tile (8 f4/thread) of channel c; stash first STASH f4
// into buf (thread-private slots, no sync needed).
__device__ __forceinline__ void reduce_tile(
    const float4* __restrict__ in, size_t base, int c, float4* buf,
    float* sh_s, float* sh_q, int tid, int lane, int wid)
{
    float s = 0.0f, q = 0.0f;
    {
        float4 v[4];
        #pragma unroll
        for (int k = 0; k < 4; k++) v[k] = in[base + k * TPB];
        #pragma unroll
        for (int k = 0; k < STASH; k++) buf[k * TPB + tid] = v[k];
        #pragma unroll
        for (int k = 0; k < 4; k++) {
            s += (v[k].x + v[k].y) + (v[k].z + v[k].w);
            q += (v[k].x * v[k].x + v[k].y * v[k].y)
               + (v[k].z * v[k].z + v[k].w * v[k].w);
        }
        #pragma unroll
        for (int k = 0; k < 4; k++) v[k] = in[base + (k + 4) * TPB];
        #pragma unroll
        for (int k = 0; k < 4; k++) {
            s += (v[k].x + v[k].y) + (v[k].z + v[k].w);
            q += (v[k].x * v[k].x + v[k].y * v[k].y)
               + (v[k].z * v[k].z + v[k].w * v[k].w);
        }
    }

    #pragma unroll
    for (int off = 16; off > 0; off >>= 1) {
        s += __shfl_down_sync(0xffffffffu, s, off);
        q += __shfl_down_sync(0xffffffffu, q, off);
    }
    if (lane == 0) { sh_s[wid] = s; sh_q[wid] = q; }
    __syncthreads();

    if (wid == 0) {
        s = (lane < NWARP) ? sh_s[lane] : 0.0f;
        q = (lane < NWARP) ? sh_q[lane] : 0.0f;
        #pragma unroll
        for (int off = 8; off > 0; off >>= 1) {
            s += __shfl_down_sync(0xffffffffu, s, off);
            q += __shfl_down_sync(0xffffffffu, q, off);
        }
        if (lane == 0) {
            atomicAdd(&g_sum[c], s);
            atomicAdd(&g_sq [c], q);
            __threadfence();
            const int old = atomicAdd(&g_done[c], 1);
            if (old == BPC - 1) {
                __threadfence();
                const float invN = 1.0f / (float)(NB * HW4 * 4);
                const float mean = g_sum[c] * invN;
                const float rstd = rsqrtf(g_sq[c] * invN - mean * mean + EPS);
                g_scale[c] = rstd;
                g_bias [c] = -mean * rstd;
                __threadfence();
                atomicExch(&g_ready[c], 1);
            }
        }
    }
    __syncthreads();   // sh_s/sh_q safe for reuse
}

__global__ void __launch_bounds__(TPB, 4)
fused_kernel(const float4* __restrict__ in, float4* __restrict__ out) {
    const int tid  = threadIdx.x;
    const int lane = tid & 31;
    const int wid  = tid >> 5;

    // 64 blocks per channel; tile = quarter of one (n,c) slice (64 KB).
    const int cidx = blockIdx.x >> 6;          // channel within round [0,8)
    const int b    = blockIdx.x & 63;
    const int n    = b >> 2;
    const int hw0  = (b & 3) * 4096;

    __shared__ float  sh_s[NWARP], sh_q[NWARP];
    __shared__ float  sh_sb[2];
    __shared__ float4 buf[2][STASH * TPB];     // 2 x 24 KB parity stash

    const size_t tbase = (size_t)n * SLICE4 + hw0 + tid;

    // ── pipeline fill: reduce round 0 (stash -> buf[0]) ──
    reduce_tile(in, tbase + (size_t)cidx * HW4, cidx, buf[0],
                sh_s, sh_q, tid, lane, wid);

    for (int g = 0; g < NR; g++) {
        const int c = g * CPR + cidx;

        // ── reduce next round first (stash -> buf[(g+1)&1]; hides the wait) ──
        if (g + 1 < NR) {
            const int cn = (g + 1) * CPR + cidx;
            reduce_tile(in, tbase + (size_t)cn * HW4, cn, buf[(g + 1) & 1],
                        sh_s, sh_q, tid, lane, wid);
        }

        // ── wait for my channel's stats (usually already set) ──
        if (tid == 0) {
            while (*((volatile int*)&g_ready[c]) == 0) __nanosleep(32);
            __threadfence();
            sh_sb[0] = g_scale[c];
            sh_sb[1] = g_bias [c];
        }
        __syncthreads();
        const float scale = sh_sb[0];
        const float bias  = sh_sb[1];

        // ── normalize round g: first STASH f4 from smem, rest from global ──
        const size_t base = tbase + (size_t)c * HW4;
        const float4* myb = buf[g & 1];
        #pragma unroll
        for (int k = 0; k < STASH; k++) {
            float4 v = myb[k * TPB + tid];
            float4 o;
            o.x = fmaf(v.x, scale, bias);
            o.y = fmaf(v.y, scale, bias);
            o.z = fmaf(v.z, scale, bias);
            o.w = fmaf(v.w, scale, bias);
            out[base + k * TPB] = o;
        }
        #pragma unroll
        for (int k = STASH; k < ITERS; k++) {
            const size_t idx = base + k * TPB;
            float4 v = in[idx];
            float4 o;
            o.x = fmaf(v.x, scale, bias);
            o.y = fmaf(v.y, scale, bias);
            o.z = fmaf(v.z, scale, bias);
            o.w = fmaf(v.w, scale, bias);
            out[idx] = o;
        }
        __syncthreads();   // keep warps phase-locked (sh_sb reuse next round)
    }

    // ── self-reset for next graph replay (after final flag use) ──
    if (tid == 0) {
        __threadfence();
        const int old = atomicAdd(&g_fin, 1);
        if (old == NBLK - 1) {
            #pragma unroll
            for (int t = 0; t < NC; t++) {
                g_sum[t] = 0.0f; g_sq[t] = 0.0f;
                g_done[t] = 0;   g_ready[t] = 0;
            }
            g_fin = 0;
            __threadfence();
        }
    }
}

extern "C" void kernel_launch(void* const* d_in, const int* in_sizes, int n_in,
                              void* d_out, int out_size) {
    const float4* in  = (const float4*)d_in[0];
    float4*       out = (float4*)d_out;

    fused_kernel<<<NBLK, TPB>>>(in, out);
}

// round 17
// speedup vs baseline: 1.1367x; 1.1367x over previous
#include <cuda_runtime.h>

// inputs: float32 [16, 64, 256, 256] NCHW
#define NB      16
#define NC      64
#define HW4     16384                 // float4 per (n,c) slice
#define SLICE4  (NC * HW4)
#define TPB     512
#define NWARP   (TPB / 32)            // 16
#define EPS     1e-5f

#define NR      8                     // rounds (channel groups of 8)
#define CPR     8                     // channels per round
#define BPC     64                    // blocks per channel
#define NBLK    512                   // all co-resident (148 SMs * 4 slots)
#define ITERS   8                     // float4 per thread per tile (64 KB tile)
#define STASH   2                     // float4 per thread stashed in smem
                                      // smem: 2*2*512*16B = 32 KB/block; x4 = 128 KB/SM

// Zero-initialized device state; kernel restores zeros before exiting.
__device__ float g_sum[NC];
__device__ float g_sq [NC];
__device__ float g_scale[NC];
__device__ float g_bias [NC];
__device__ int   g_done [NC];
__device__ int   g_ready[NC];
__device__ int   g_fin;

// Reduce one 64 KB tile (8 f4/thread) of channel c; stash first STASH f4
// into buf (thread-private slots, no sync needed).
__device__ __forceinline__ void reduce_tile(
    const float4* __restrict__ in, size_t base, int c, float4* buf,
    float* sh_s, float* sh_q, int tid, int lane, int wid)
{
    float s = 0.0f, q = 0.0f;
    {
        float4 v[4];
        #pragma unroll
        for (int k = 0; k < 4; k++) v[k] = in[base + k * TPB];
        #pragma unroll
        for (int k = 0; k < STASH; k++) buf[k * TPB + tid] = v[k];
        #pragma unroll
        for (int k = 0; k < 4; k++) {
            s += (v[k].x + v[k].y) + (v[k].z + v[k].w);
            q += (v[k].x * v[k].x + v[k].y * v[k].y)
               + (v[k].z * v[k].z + v[k].w * v[k].w);
        }
        #pragma unroll
        for (int k = 0; k < 4; k++) v[k] = in[base + (k + 4) * TPB];
        #pragma unroll
        for (int k = 0; k < 4; k++) {
            s += (v[k].x + v[k].y) + (v[k].z + v[k].w);
            q += (v[k].x * v[k].x + v[k].y * v[k].y)
               + (v[k].z * v[k].z + v[k].w * v[k].w);
        }
    }

    #pragma unroll
    for (int off = 16; off > 0; off >>= 1) {
        s += __shfl_down_sync(0xffffffffu, s, off);
        q += __shfl_down_sync(0xffffffffu, q, off);
    }
    if (lane == 0) { sh_s[wid] = s; sh_q[wid] = q; }
    __syncthreads();

    if (wid == 0) {
        s = (lane < NWARP) ? sh_s[lane] : 0.0f;
        q = (lane < NWARP) ? sh_q[lane] : 0.0f;
        #pragma unroll
        for (int off = 8; off > 0; off >>= 1) {
            s += __shfl_down_sync(0xffffffffu, s, off);
            q += __shfl_down_sync(0xffffffffu, q, off);
        }
        if (lane == 0) {
            atomicAdd(&g_sum[c], s);
            atomicAdd(&g_sq [c], q);
            __threadfence();
            const int old = atomicAdd(&g_done[c], 1);
            if (old == BPC - 1) {
                __threadfence();
                const float invN = 1.0f / (float)(NB * HW4 * 4);
                const float mean = g_sum[c] * invN;
                const float rstd = rsqrtf(g_sq[c] * invN - mean * mean + EPS);
                g_scale[c] = rstd;
                g_bias [c] = -mean * rstd;
                __threadfence();
                atomicExch(&g_ready[c], 1);
            }
        }
    }
    __syncthreads();   // sh_s/sh_q safe for reuse
}

__global__ void __launch_bounds__(TPB, 4)
fused_kernel(const float4* __restrict__ in, float4* __restrict__ out) {
    const int tid  = threadIdx.x;
    const int lane = tid & 31;
    const int wid  = tid >> 5;

    // 64 blocks per channel; tile = quarter of one (n,c) slice (64 KB).
    const int cidx = blockIdx.x >> 6;          // channel within round [0,8)
    const int b    = blockIdx.x & 63;
    const int n    = b >> 2;
    const int hw0  = (b & 3) * 4096;

    __shared__ float  sh_s[NWARP], sh_q[NWARP];
    __shared__ float  sh_sb[2];
    __shared__ float4 buf[2][STASH * TPB];     // 2 x 16 KB parity stash

    const size_t tbase = (size_t)n * SLICE4 + hw0 + tid;

    // ── pipeline fill: reduce round 0 (stash -> buf[0]) ──
    reduce_tile(in, tbase + (size_t)cidx * HW4, cidx, buf[0],
                sh_s, sh_q, tid, lane, wid);

    for (int g = 0; g < NR; g++) {
        const int c = g * CPR + cidx;

        // ── reduce next round first (stash -> buf[(g+1)&1]; hides the wait) ──
        if (g + 1 < NR) {
            const int cn = (g + 1) * CPR + cidx;
            reduce_tile(in, tbase + (size_t)cn * HW4, cn, buf[(g + 1) & 1],
                        sh_s, sh_q, tid, lane, wid);
        }

        // ── wait for my channel's stats (usually already set) ──
        if (tid == 0) {
            while (*((volatile int*)&g_ready[c]) == 0) __nanosleep(32);
            __threadfence();
            sh_sb[0] = g_scale[c];
            sh_sb[1] = g_bias [c];
        }
        __syncthreads();
        const float scale = sh_sb[0];
        const float bias  = sh_sb[1];

        // ── normalize round g: first STASH f4 from smem, the other 6 from
        //    global in two front-batched groups of 3 (__ldcg: no L1 alloc) ──
        const size_t base = tbase + (size_t)c * HW4;
        const float4* myb = buf[g & 1];
        #pragma unroll
        for (int k = 0; k < STASH; k++) {
            float4 v = myb[k * TPB + tid];
            float4 o;
            o.x = fmaf(v.x, scale, bias);
            o.y = fmaf(v.y, scale, bias);
            o.z = fmaf(v.z, scale, bias);
            o.w = fmaf(v.w, scale, bias);
            out[base + k * TPB] = o;
        }
        #pragma unroll
        for (int grp = 0; grp < 2; grp++) {
            const int k0 = STASH + grp * 3;
            float4 v[3];
            #pragma unroll
            for (int j = 0; j < 3; j++) v[j] = __ldcg(&in[base + (k0 + j) * TPB]);
            #pragma unroll
            for (int j = 0; j < 3; j++) {
                float4 o;
                o.x = fmaf(v[j].x, scale, bias);
                o.y = fmaf(v[j].y, scale, bias);
                o.z = fmaf(v[j].z, scale, bias);
                o.w = fmaf(v[j].w, scale, bias);
                out[base + (k0 + j) * TPB] = o;
            }
        }
        __syncthreads();   // keep warps phase-locked (sh_sb reuse next round)
    }

    // ── self-reset for next graph replay (after final flag use) ──
    if (tid == 0) {
        __threadfence();
        const int old = atomicAdd(&g_fin, 1);
        if (old == NBLK - 1) {
            #pragma unroll
            for (int t = 0; t < NC; t++) {
                g_sum[t] = 0.0f; g_sq[t] = 0.0f;
                g_done[t] = 0;   g_ready[t] = 0;
            }
            g_fin = 0;
            __threadfence();
        }
    }
}

extern "C" void kernel_launch(void* const* d_in, const int* in_sizes, int n_in,
                              void* d_out, int out_size) {
    const float4* in  = (const float4*)d_in[0];
    float4*       out = (float4*)d_out;

    fused_kernel<<<NBLK, TPB>>>(in, out);
}